// round 6
// baseline (speedup 1.0000x reference)
#include <cuda_runtime.h>
#include <cfloat>

#define EPS_S   0.01f
#define INV_EPS 100.0f
#define LOG_MU  -6.93146200f   /* log(1/1024 + 1e-8) */
#define BN_EPS  1e-5f

typedef unsigned long long ull;

/* ---------------- packed fp32x2 primitives (Blackwell f32x2 pipe) ---------- */
__device__ __forceinline__ ull ffma2(ull a, ull b, ull c) {
    ull d;
    asm("fma.rn.f32x2 %0, %1, %2, %3;" : "=l"(d) : "l"(a), "l"(b), "l"(c));
    return d;
}
__device__ __forceinline__ ull pk2(float lo, float hi) {
    ull r;
    asm("mov.b64 %0, {%1, %2};" : "=l"(r)
        : "r"(__float_as_uint(lo)), "r"(__float_as_uint(hi)));
    return r;
}
__device__ __forceinline__ float2 up2(ull v) {
    unsigned int lo, hi;
    asm("mov.b64 {%0, %1}, %2;" : "=r"(lo), "=r"(hi) : "l"(v));
    float2 f; f.x = __uint_as_float(lo); f.y = __uint_as_float(hi);
    return f;
}

/* ---------------- scratch (device globals: no allocs allowed) -------------- */
__device__ float g_C[4 * 1024 * 1024];
__device__ float g_u[4096], g_v[4096];
__device__ float g_rnx[4096], g_rny[4096];
__device__ float g_t[4 * 512 * 1024];
__device__ float g_a1[4 * 256 * 1024];
__device__ float g_a2[4 * 256 * 1024];
__device__ float g_alpha[4 * 512 * 1024];
__device__ float g_cm[2048], g_rs[2048];
__device__ float g_scale[512], g_shift[512];

/* ---------------- small helpers ---------------- */
__device__ __forceinline__ float warpMax(float v) {
    #pragma unroll
    for (int o = 16; o; o >>= 1) v = fmaxf(v, __shfl_xor_sync(0xffffffffu, v, o));
    return v;
}
__device__ __forceinline__ float warpSum(float v) {
    #pragma unroll
    for (int o = 16; o; o >>= 1) v += __shfl_xor_sync(0xffffffffu, v, o);
    return v;
}

/* ---------------- 1/||x|| per point ---------------- */
__global__ __launch_bounds__(256) void rownorm(const float* __restrict__ x,
                                               float* __restrict__ rn) {
    int b = blockIdx.y;
    int i = blockIdx.x * 256 + threadIdx.x;
    const float* p = x + ((size_t)b * 512 << 10) + i;
    float s = 0.f;
    #pragma unroll 8
    for (int d = 0; d < 512; d++) {
        float v = p[(size_t)d << 10];
        s = fmaf(v, v, s);
    }
    rn[(b << 10) + i] = rsqrtf(s);
}

/* ---------------- SGEMM TN (f32x2): C[i,j] = 1 - rnx rny sum A[d,i]B[d,j] -- */
#define BM 128
#define BN 128
#define BK 16
__global__ __launch_bounds__(256) void gemm_tn_cost(
    const float* __restrict__ A, const float* __restrict__ B,
    const float* __restrict__ rnx, const float* __restrict__ rny,
    float* __restrict__ Cout) {
    int b = blockIdx.z;
    const float* Ab = A + (size_t)b * 512 * 1024;
    const float* Bb = B + (size_t)b * 512 * 1024;
    float* Cb = Cout + (size_t)b * 1024 * 1024;
    __shared__ float As[BK][BM];
    __shared__ float Bs[BK][BN];
    int tid = threadIdx.x;
    int tx = tid & 15, ty = tid >> 4;
    int m0 = blockIdx.x * BM, n0 = blockIdx.y * BN;
    ull acc2[8][4];
    #pragma unroll
    for (int i = 0; i < 8; i++)
        #pragma unroll
        for (int j = 0; j < 4; j++) acc2[i][j] = 0ULL;

    for (int k0 = 0; k0 < 512; k0 += BK) {
        #pragma unroll
        for (int l = 0; l < 2; l++) {
            int idx = tid + l * 256;
            int k = idx >> 5, m4 = idx & 31;
            *(float4*)&As[k][m4 * 4] =
                *(const float4*)(Ab + (size_t)(k0 + k) * 1024 + m0 + m4 * 4);
            *(float4*)&Bs[k][m4 * 4] =
                *(const float4*)(Bb + (size_t)(k0 + k) * 1024 + n0 + m4 * 4);
        }
        __syncthreads();
        #pragma unroll
        for (int k = 0; k < BK; k++) {
            float a[8];
            *(float4*)a       = *(float4*)&As[k][ty * 8];
            *(float4*)(a + 4) = *(float4*)&As[k][ty * 8 + 4];
            ull ad[8];
            #pragma unroll
            for (int i = 0; i < 8; i++) ad[i] = pk2(a[i], a[i]);
            const ull* bq = (const ull*)&Bs[k][tx * 8];
            ull bd[4];
            #pragma unroll
            for (int j = 0; j < 4; j++) bd[j] = bq[j];
            #pragma unroll
            for (int i = 0; i < 8; i++)
                #pragma unroll
                for (int j = 0; j < 4; j++)
                    acc2[i][j] = ffma2(ad[i], bd[j], acc2[i][j]);
        }
        __syncthreads();
    }
    #pragma unroll
    for (int i = 0; i < 8; i++) {
        int m = m0 + ty * 8 + i;
        float rx = rnx[(b << 10) + m];
        float vals[8];
        #pragma unroll
        for (int j = 0; j < 4; j++) {
            float2 q = up2(acc2[i][j]);
            vals[2 * j] = q.x; vals[2 * j + 1] = q.y;
        }
        float4 o0, o1;
        #pragma unroll
        for (int j = 0; j < 8; j++) {
            int n = n0 + tx * 8 + j;
            float v = 1.f - rx * rny[(b << 10) + n] * vals[j];
            if (j < 4) ((float*)&o0)[j] = v; else ((float*)&o1)[j - 4] = v;
        }
        *(float4*)(Cb + (size_t)m * 1024 + n0 + tx * 8)     = o0;
        *(float4*)(Cb + (size_t)m * 1024 + n0 + tx * 8 + 4) = o1;
    }
}

/* ---- SGEMM NT (f32x2), fused pi: T[d,i]=sum_j A[d,j]*exp((u+v-C)/eps)*1024 */
__global__ __launch_bounds__(256) void gemm_nt_t(
    const float* __restrict__ A,
    const float* __restrict__ Cc,
    const float* __restrict__ u, const float* __restrict__ v,
    float* __restrict__ T) {
    int b = blockIdx.z;
    const float* Ab = A + (size_t)b * 512 * 1024;
    const float* Pb = Cc + (size_t)b * 1024 * 1024;
    const float* ub = u + (b << 10);
    const float* vb = v + (b << 10);
    float* Tb = T + (size_t)b * 512 * 1024;
    __shared__ float As[BK][BM];
    __shared__ float Bs[BK][BN];
    int tid = threadIdx.x;
    int tx = tid & 15, ty = tid >> 4;
    int m0 = blockIdx.x * BM, n0 = blockIdx.y * BN;
    ull acc2[8][4];
    #pragma unroll
    for (int i = 0; i < 8; i++)
        #pragma unroll
        for (int j = 0; j < 4; j++) acc2[i][j] = 0ULL;

    for (int k0 = 0; k0 < 1024; k0 += BK) {
        #pragma unroll
        for (int l = 0; l < 2; l++) {
            int idx = tid + l * 256;
            int m = idx >> 2, k4 = idx & 3;
            float4 va = *(const float4*)(Ab + (size_t)(m0 + m) * 1024 + k0 + k4 * 4);
            As[k4 * 4 + 0][m] = va.x; As[k4 * 4 + 1][m] = va.y;
            As[k4 * 4 + 2][m] = va.z; As[k4 * 4 + 3][m] = va.w;
            float4 vc = *(const float4*)(Pb + (size_t)(n0 + m) * 1024 + k0 + k4 * 4);
            float ui = ub[n0 + m];
            float4 vv = *(const float4*)(vb + k0 + k4 * 4);
            Bs[k4 * 4 + 0][m] = __expf((ui + vv.x - vc.x) * INV_EPS) * 1024.f;
            Bs[k4 * 4 + 1][m] = __expf((ui + vv.y - vc.y) * INV_EPS) * 1024.f;
            Bs[k4 * 4 + 2][m] = __expf((ui + vv.z - vc.z) * INV_EPS) * 1024.f;
            Bs[k4 * 4 + 3][m] = __expf((ui + vv.w - vc.w) * INV_EPS) * 1024.f;
        }
        __syncthreads();
        #pragma unroll
        for (int k = 0; k < BK; k++) {
            float a[8];
            *(float4*)a       = *(float4*)&As[k][ty * 8];
            *(float4*)(a + 4) = *(float4*)&As[k][ty * 8 + 4];
            ull ad[8];
            #pragma unroll
            for (int i = 0; i < 8; i++) ad[i] = pk2(a[i], a[i]);
            const ull* bq = (const ull*)&Bs[k][tx * 8];
            ull bd[4];
            #pragma unroll
            for (int j = 0; j < 4; j++) bd[j] = bq[j];
            #pragma unroll
            for (int i = 0; i < 8; i++)
                #pragma unroll
                for (int j = 0; j < 4; j++)
                    acc2[i][j] = ffma2(ad[i], bd[j], acc2[i][j]);
        }
        __syncthreads();
    }
    #pragma unroll
    for (int i = 0; i < 8; i++) {
        int m = m0 + ty * 8 + i;
        float4 o0, o1;
        #pragma unroll
        for (int j = 0; j < 4; j++) {
            float2 q = up2(acc2[i][j]);
            if (j < 2) { ((float*)&o0)[2 * j] = q.x; ((float*)&o0)[2 * j + 1] = q.y; }
            else       { ((float*)&o1)[2 * (j - 2)] = q.x; ((float*)&o1)[2 * (j - 2) + 1] = q.y; }
        }
        *(float4*)(Tb + (size_t)m * 1024 + n0 + tx * 8)     = o0;
        *(float4*)(Tb + (size_t)m * 1024 + n0 + tx * 8 + 4) = o1;
    }
}

/* ---------------- Sinkhorn ---------------- */
__global__ void zero_uv(float* u, float* v) {
    int i = blockIdx.x * blockDim.x + threadIdx.x;
    if (i < 4096) { u[i] = 0.f; v[i] = 0.f; }
}

__global__ __launch_bounds__(256) void u_update(const float* __restrict__ C,
                                                const float* __restrict__ v,
                                                float* __restrict__ u) {
    int b = blockIdx.y, i = blockIdx.x, t = threadIdx.x;
    const float4* C4 = (const float4*)(C + ((size_t)(b << 10) + i) * 1024);
    const float4* V4 = (const float4*)(v + (b << 10));
    float4 c = C4[t], vv = V4[t];
    float x0 = (vv.x - c.x) * INV_EPS;
    float x1 = (vv.y - c.y) * INV_EPS;
    float x2 = (vv.z - c.z) * INV_EPS;
    float x3 = (vv.w - c.w) * INV_EPS;
    float mx = fmaxf(fmaxf(x0, x1), fmaxf(x2, x3));
    __shared__ float redm[8], redq[8];
    mx = warpMax(mx);
    if ((t & 31) == 0) redm[t >> 5] = mx;
    __syncthreads();
    if (t < 32) {
        float z = (t < 8) ? redm[t] : -FLT_MAX;
        #pragma unroll
        for (int o = 4; o; o >>= 1) z = fmaxf(z, __shfl_xor_sync(0xffffffffu, z, o));
        if (t == 0) redm[0] = z;
    }
    __syncthreads();
    float bm = redm[0];
    float s = __expf(x0 - bm) + __expf(x1 - bm) + __expf(x2 - bm) + __expf(x3 - bm);
    s = warpSum(s);
    if ((t & 31) == 0) redq[t >> 5] = s;
    __syncthreads();
    if (t == 0) {
        float z = 0.f;
        #pragma unroll
        for (int q = 0; q < 8; q++) z += redq[q];
        u[(b << 10) + i] = EPS_S * (LOG_MU - (bm + __logf(z)));
    }
}

__global__ __launch_bounds__(256) void v_update(const float* __restrict__ C,
                                                const float* __restrict__ u,
                                                float* __restrict__ v) {
    int b = blockIdx.y;
    int tx = threadIdx.x, ty = threadIdx.y;
    int j = blockIdx.x * 32 + tx;
    const float* p = C + (size_t)b * 1048576 + j;
    const float* ub = u + (b << 10);
    float m0 = -FLT_MAX, s0 = 0.f, m1 = -FLT_MAX, s1 = 0.f;
    for (int i = ty; i < 1024; i += 16) {
        float xa = (ub[i] - p[(size_t)i << 10]) * INV_EPS;
        float xb = (ub[i + 8] - p[(size_t)(i + 8) << 10]) * INV_EPS;
        float n0 = fmaxf(m0, xa);
        s0 = s0 * __expf(m0 - n0) + __expf(xa - n0); m0 = n0;
        float n1 = fmaxf(m1, xb);
        s1 = s1 * __expf(m1 - n1) + __expf(xb - n1); m1 = n1;
    }
    float mm = fmaxf(m0, m1);
    float ss = s0 * __expf(m0 - mm) + s1 * __expf(m1 - mm);
    __shared__ float sm[8][32], sq[8][32];
    sm[ty][tx] = mm; sq[ty][tx] = ss;
    __syncthreads();
    if (ty == 0) {
        float M = mm, S = ss;
        #pragma unroll
        for (int q = 1; q < 8; q++) {
            float m2 = sm[q][tx], s2 = sq[q][tx];
            float nm = fmaxf(M, m2);
            S = S * __expf(M - nm) + s2 * __expf(m2 - nm);
            M = nm;
        }
        v[(b << 10) + j] = EPS_S * (LOG_MU - (M + __logf(S)));
    }
}

/* ---------------- per-(b,c) mean / 1/std of content ---------------- */
__global__ __launch_bounds__(128) void cmstd(const float* __restrict__ x,
                                             float* __restrict__ cm,
                                             float* __restrict__ rs) {
    int bc = blockIdx.x, t = threadIdx.x;
    const float* p = x + ((size_t)bc << 10);
    float s = 0.f, q = 0.f;
    #pragma unroll
    for (int l = 0; l < 8; l++) {
        float v = p[t + l * 128];
        s += v; q = fmaf(v, v, q);
    }
    s = warpSum(s); q = warpSum(q);
    __shared__ float rsm[4], rqm[4];
    if ((t & 31) == 0) { rsm[t >> 5] = s; rqm[t >> 5] = q; }
    __syncthreads();
    if (t == 0) {
        float S = rsm[0] + rsm[1] + rsm[2] + rsm[3];
        float Q = rqm[0] + rqm[1] + rqm[2] + rqm[3];
        float mean = S * (1.f / 1024.f);
        float var = Q * (1.f / 1024.f) - mean * mean;
        cm[bc] = mean;
        rs[bc] = rsqrtf(fmaxf(var, 0.f) + 1e-5f);
    }
}

/* ---------------- BatchNorm stats (train mode): scale/shift ---------------- */
__global__ __launch_bounds__(256) void bnstats(const float* __restrict__ x,
                                               const float* __restrict__ g,
                                               const float* __restrict__ be,
                                               int CO, float* __restrict__ scale,
                                               float* __restrict__ shift) {
    int c = blockIdx.x, t = threadIdx.x;
    float s = 0.f, q = 0.f;
    #pragma unroll
    for (int l = 0; l < 16; l++) {
        int idx = t + (l << 8);
        int bb = idx >> 10, p = idx & 1023;
        float v = x[((size_t)(bb * CO + c) << 10) + p];
        s += v; q = fmaf(v, v, q);
    }
    s = warpSum(s); q = warpSum(q);
    __shared__ float rsm[8], rqm[8];
    if ((t & 31) == 0) { rsm[t >> 5] = s; rqm[t >> 5] = q; }
    __syncthreads();
    if (t == 0) {
        float S = 0.f, Q = 0.f;
        #pragma unroll
        for (int w = 0; w < 8; w++) { S += rsm[w]; Q += rqm[w]; }
        float mean = S * (1.f / 4096.f);
        float var = Q * (1.f / 4096.f) - mean * mean;
        float sc = g[c] * rsqrtf(fmaxf(var, 0.f) + BN_EPS);
        scale[c] = sc;
        shift[c] = be[c] - mean * sc;
    }
}

/* ---------------- t = alpha * (content - cm) * rs + t ---------------- */
__global__ __launch_bounds__(256) void blend(float* __restrict__ t,
                                             const float* __restrict__ alpha,
                                             const float* __restrict__ content,
                                             const float* __restrict__ cm,
                                             const float* __restrict__ rs, int n4) {
    int i = blockIdx.x * 256 + threadIdx.x;
    if (i >= n4) return;
    int ch = i >> 8;
    float m = cm[ch], r = rs[ch];
    float4 a = ((const float4*)alpha)[i];
    float4 x = ((const float4*)content)[i];
    float4 tv = ((float4*)t)[i];
    tv.x = fmaf(a.x, (x.x - m) * r, tv.x);
    tv.y = fmaf(a.y, (x.y - m) * r, tv.y);
    tv.z = fmaf(a.z, (x.z - m) * r, tv.z);
    tv.w = fmaf(a.w, (x.w - m) * r, tv.w);
    ((float4*)t)[i] = tv;
}

/* ---------------- direct 3x3 conv, f32x2 packed pixel pairs -----------------
   Thread owns 2 adjacent pixels; weights smem-duplicated as (w,w) float2 so
   packed operands load directly. Optional fused input affine (BN apply).     */
template <int OCT, int SROWS, int NT, int CIT>
__global__ __launch_bounds__(NT) void conv3x3(
    const float* __restrict__ src0, const float* __restrict__ src1, int csplit,
    const float* __restrict__ sc, const float* __restrict__ sh,
    int CI, int CO, const float* __restrict__ W, const float* __restrict__ bias,
    float* __restrict__ out, int relu) {
    static_assert(SROWS * 32 == 2 * NT, "pixel-pair mapping requires NPIX == 2*NT");
    __shared__ float  s_in[CIT][SROWS + 2][34];
    __shared__ float2 s_w2[CIT][9][OCT];
    int b = blockIdx.x, oc0 = blockIdx.y * OCT, r0 = blockIdx.z * SROWS;
    int tid = threadIdx.x;
    int row = tid >> 4, col0 = (tid & 15) * 2;

    ull acc2[OCT];
    #pragma unroll
    for (int o = 0; o < OCT; o++) acc2[o] = 0ULL;

    const int TOTIN = CIT * (SROWS + 2) * 34;
    const int TW = CIT * 9 * OCT;
    int use_aff = (sc != nullptr);

    #pragma unroll 1
    for (int ci0 = 0; ci0 < CI; ci0 += CIT) {
        #pragma unroll 1
        for (int idx = tid; idx < TOTIN; idx += NT) {
            int ci = idx / ((SROWS + 2) * 34);
            int rem = idx - ci * ((SROWS + 2) * 34);
            int r = rem / 34, c = rem - r * 34;
            int gy = r0 + r - 1, gx = c - 1;
            float v = 0.f;
            if ((unsigned)gy < 32u && (unsigned)gx < 32u) {
                int cig = ci0 + ci;
                const float* s = (cig < csplit)
                    ? (src0 + ((size_t)(b * csplit + cig) << 10))
                    : (src1 + ((size_t)(b * (CI - csplit) + (cig - csplit)) << 10));
                v = s[(gy << 5) + gx];
                if (use_aff) v = fmaf(v, sc[cig], sh[cig]);
            }
            (&s_in[0][0][0])[idx] = v;
        }
        #pragma unroll 1
        for (int idx = tid; idx < TW; idx += NT) {
            int ci = idx / (9 * OCT);
            int rem = idx - ci * (9 * OCT);
            int k = rem / OCT, oc = rem - k * OCT;
            float wv = 0.f;
            if (oc0 + oc < CO)
                wv = W[((size_t)(oc0 + oc) * CI + ci0 + ci) * 9 + k];
            (&s_w2[0][0][0])[idx] = make_float2(wv, wv);
        }
        __syncthreads();
        #pragma unroll 1
        for (int ci = 0; ci < CIT; ci++) {
            #pragma unroll
            for (int ky = 0; ky < 3; ky++) {
                const float2* rp = (const float2*)&s_in[ci][row + ky][col0];
                float2 pa = rp[0], pc = rp[1];
                ull p0 = pk2(pa.x, pa.y);
                ull p1 = pk2(pa.y, pc.x);
                ull p2 = pk2(pc.x, pc.y);
                #pragma unroll
                for (int kx = 0; kx < 3; kx++) {
                    ull pp = (kx == 0) ? p0 : ((kx == 1) ? p1 : p2);
                    const ull* wq = (const ull*)&s_w2[ci][ky * 3 + kx][0];
                    #pragma unroll
                    for (int o = 0; o < OCT; o++)
                        acc2[o] = ffma2(pp, wq[o], acc2[o]);
                }
            }
        }
        __syncthreads();
    }
    #pragma unroll
    for (int o = 0; o < OCT; o++) {
        if (oc0 + o >= CO) break;
        float bi = bias[oc0 + o];
        float2 q = up2(acc2[o]);
        q.x += bi; q.y += bi;
        if (relu) { q.x = fmaxf(q.x, 0.f); q.y = fmaxf(q.y, 0.f); }
        *(float2*)(out + ((size_t)(b * CO + oc0 + o) << 10) + (r0 + row) * 32 + col0) = q;
    }
}

/* ---------------- host orchestration ---------------- */
extern "C" void kernel_launch(void* const* d_in, const int* in_sizes, int n_in,
                              void* d_out, int out_size) {
    const float* content = (const float*)d_in[0];
    const float* style   = (const float*)d_in[1];
    const float* w1 = (const float*)d_in[2];  const float* b1 = (const float*)d_in[3];
    const float* g1 = (const float*)d_in[4];  const float* be1 = (const float*)d_in[5];
    const float* w2 = (const float*)d_in[6];  const float* b2 = (const float*)d_in[7];
    const float* g2 = (const float*)d_in[8];  const float* be2 = (const float*)d_in[9];
    const float* w3 = (const float*)d_in[10]; const float* b3 = (const float*)d_in[11];
    const float* dw = (const float*)d_in[12]; const float* db = (const float*)d_in[13];
    float* out = (float*)d_out;
    (void)in_sizes; (void)n_in; (void)out_size;

    float *pC, *pu, *pv, *prnx, *prny, *pt, *pa1, *pa2, *palpha, *pcm, *prs, *pscale, *pshift;
    cudaGetSymbolAddress((void**)&pC, g_C);
    cudaGetSymbolAddress((void**)&pu, g_u);
    cudaGetSymbolAddress((void**)&pv, g_v);
    cudaGetSymbolAddress((void**)&prnx, g_rnx);
    cudaGetSymbolAddress((void**)&prny, g_rny);
    cudaGetSymbolAddress((void**)&pt, g_t);
    cudaGetSymbolAddress((void**)&pa1, g_a1);
    cudaGetSymbolAddress((void**)&pa2, g_a2);
    cudaGetSymbolAddress((void**)&palpha, g_alpha);
    cudaGetSymbolAddress((void**)&pcm, g_cm);
    cudaGetSymbolAddress((void**)&prs, g_rs);
    cudaGetSymbolAddress((void**)&pscale, g_scale);
    cudaGetSymbolAddress((void**)&pshift, g_shift);

    /* cosine-cost matrix */
    rownorm<<<dim3(4, 4), 256>>>(content, prnx);
    rownorm<<<dim3(4, 4), 256>>>(style, prny);
    gemm_tn_cost<<<dim3(8, 8, 4), 256>>>(content, style, prnx, prny, pC);

    /* Sinkhorn, 20 iterations */
    zero_uv<<<16, 256>>>(pu, pv);
    for (int it = 0; it < 20; it++) {
        u_update<<<dim3(1024, 4), 256>>>(pC, pv, pu);
        v_update<<<dim3(32, 4), dim3(32, 8)>>>(pC, pu, pv);
    }

    /* t = pi @ style_points, exp fused into B-tile load */
    gemm_nt_t<<<dim3(4, 8, 4), 256>>>(style, pC, pu, pv, pt);

    /* content per-channel mean/std */
    cmstd<<<2048, 128>>>(content, pcm, prs);

    /* alpha predictor (BN-apply fused into next conv's input load) */
    conv3x3<8, 16, 256, 8><<<dim3(4, 32, 2), 256>>>(pt, content, 512,
        nullptr, nullptr, 1024, 256, w1, b1, pa1, 1);
    bnstats<<<256, 256>>>(pa1, g1, be1, 256, pscale, pshift);
    conv3x3<8, 16, 256, 8><<<dim3(4, 32, 2), 256>>>(pa1, pa1, 256,
        pscale, pshift, 256, 256, w2, b2, pa2, 1);
    bnstats<<<256, 256>>>(pa2, g2, be2, 256, pscale, pshift);
    conv3x3<8, 16, 256, 8><<<dim3(4, 64, 2), 256>>>(pa2, pa2, 256,
        pscale, pshift, 256, 512, w3, b3, palpha, 0);

    /* t = alpha * c_normed + t, then decoder conv -> out */
    blend<<<2048, 256>>>(pt, palpha, content, pcm, prs, 4 * 512 * 256);
    conv3x3<4, 8, 128, 8><<<dim3(4, 1, 4), 128>>>(pt, pt, 512,
        nullptr, nullptr, 512, 3, dw, db, out, 0);
}

// round 8
// speedup vs baseline: 1.1800x; 1.1800x over previous
#include <cuda_runtime.h>
#include <cuda_bf16.h>
#include <cfloat>
#include <cstdint>

#define EPS_S   0.01f
#define INV_EPS 100.0f
#define LOG_MU  -6.93146200f   /* log(1/1024 + 1e-8) */
#define BN_EPS  1e-5f

/* ---------------- scratch (device globals: no allocs allowed) -------------- */
__device__ float g_C[4 * 1024 * 1024];
__device__ float g_u[4096], g_v[4096];
__device__ float g_rnx[4096], g_rny[4096];
__device__ float g_t[4 * 512 * 1024];
__device__ float g_a1[4 * 256 * 1024];
__device__ float g_a2[4 * 256 * 1024];
__device__ float g_alpha[4 * 512 * 1024];
__device__ float g_cm[2048], g_rs[2048];
__device__ float g_scale[512], g_shift[512];
/* bf16 split operand buffers */
__device__ unsigned short g_cTh[4 * 1024 * 512], g_cTl[4 * 1024 * 512]; /* content^T [b][i][d] */
__device__ unsigned short g_sTh[4 * 1024 * 512], g_sTl[4 * 1024 * 512]; /* style^T   [b][j][d] */
__device__ unsigned short g_sfh[4 * 512 * 1024], g_sfl[4 * 512 * 1024]; /* style     [b][d][j] */
__device__ unsigned short g_pih[4 * 1024 * 1024], g_pil[4 * 1024 * 1024]; /* pi      [b][i][j] */

__device__ __forceinline__ uint32_t smem_u32(const void* p) {
    uint32_t a;
    asm("{ .reg .u64 t; cvta.to.shared.u64 t, %1; cvt.u32.u64 %0, t; }"
        : "=r"(a) : "l"(p));
    return a;
}
__device__ __forceinline__ void ldsm_x4(uint32_t& r0, uint32_t& r1,
                                        uint32_t& r2, uint32_t& r3, uint32_t a) {
    asm volatile("ldmatrix.sync.aligned.m8n8.x4.shared.b16 {%0,%1,%2,%3}, [%4];"
                 : "=r"(r0), "=r"(r1), "=r"(r2), "=r"(r3) : "r"(a));
}
__device__ __forceinline__ void mma_bf16(float& d0, float& d1, float& d2, float& d3,
                                         uint32_t a0, uint32_t a1, uint32_t a2, uint32_t a3,
                                         uint32_t b0, uint32_t b1) {
    asm volatile(
        "mma.sync.aligned.m16n8k16.row.col.f32.bf16.bf16.f32 "
        "{%0,%1,%2,%3}, {%4,%5,%6,%7}, {%8,%9}, {%0,%1,%2,%3};"
        : "+f"(d0), "+f"(d1), "+f"(d2), "+f"(d3)
        : "r"(a0), "r"(a1), "r"(a2), "r"(a3), "r"(b0), "r"(b1));
}

/* ============ HMMA bf16 split GEMM: D[m,n] = sum_k A[m,k]B[n,k] ============
   A,B split hi+lo bf16, K-major rows. Block 128x64, 8 warps (4m x 2n),
   warp tile 32x32 (2 m16-tiles x 4 n8-tiles). K chunk 32. Row pad 40 bf16.
   EPI=0: store acc. EPI=1: store 1 - rnx[m]*rny[n]*acc.                     */
template <int EPI>
__global__ __launch_bounds__(256) void hmma_gemm(
    const unsigned short* __restrict__ Ahi, const unsigned short* __restrict__ Alo,
    const unsigned short* __restrict__ Bhi, const unsigned short* __restrict__ Blo,
    int Mtot, int Ktot,
    const float* __restrict__ rnx, const float* __restrict__ rny,
    float* __restrict__ out) {
    __shared__ unsigned short sAh[128 * 40], sAl[128 * 40];
    __shared__ unsigned short sBh[64 * 40], sBl[64 * 40];
    int tid = threadIdx.x, wid = tid >> 5, lid = tid & 31;
    int b = blockIdx.z, m0 = blockIdx.x * 128, n0 = blockIdx.y * 64;
    int wm = wid & 3, wn = wid >> 2;            /* warp tile origin */
    size_t abase = (size_t)b * Mtot * Ktot;
    size_t bbase = (size_t)b * 1024 * Ktot;     /* Ntot = 1024 always */

    uint32_t uAh = smem_u32(sAh), uAl = smem_u32(sAl);
    uint32_t uBh = smem_u32(sBh), uBl = smem_u32(sBl);

    /* ldmatrix lane->address components */
    int arow = ((lid >> 3) & 1) * 8 + (lid & 7);
    int akof = (lid >> 4) * 8;
    int brow = (lid & 7) + ((lid >> 4) & 1) * 8;
    int bkof = ((lid >> 3) & 1) * 8;

    float d[2][4][4];
    #pragma unroll
    for (int i = 0; i < 2; i++)
        #pragma unroll
        for (int j = 0; j < 4; j++)
            #pragma unroll
            for (int q = 0; q < 4; q++) d[i][j][q] = 0.f;

    for (int k0 = 0; k0 < Ktot; k0 += 32) {
        /* fill A: 128 rows x 32 bf16 (4 uint4 per row) per split */
        #pragma unroll
        for (int l = 0; l < 2; l++) {
            int idx = tid + l * 256;            /* 0..511 uint4 slots */
            int r = idx >> 2, seg = idx & 3;
            const uint4* gh = (const uint4*)(Ahi + abase + (size_t)(m0 + r) * Ktot + k0 + seg * 8);
            const uint4* gl = (const uint4*)(Alo + abase + (size_t)(m0 + r) * Ktot + k0 + seg * 8);
            *(uint4*)(sAh + r * 40 + seg * 8) = *gh;
            *(uint4*)(sAl + r * 40 + seg * 8) = *gl;
        }
        /* fill B: 64 rows x 32 bf16 per split (256 uint4 each) */
        {
            int idx = tid;                      /* 0..255 */
            int r = idx >> 2, seg = idx & 3;
            const uint4* gh = (const uint4*)(Bhi + bbase + (size_t)(n0 + r) * Ktot + k0 + seg * 8);
            const uint4* gl = (const uint4*)(Blo + bbase + (size_t)(n0 + r) * Ktot + k0 + seg * 8);
            *(uint4*)(sBh + r * 40 + seg * 8) = *gh;
            *(uint4*)(sBl + r * 40 + seg * 8) = *gl;
        }
        __syncthreads();
        #pragma unroll
        for (int ks = 0; ks < 2; ks++) {
            int kb = ks * 16;
            uint32_t ah[2][4], al[2][4];
            #pragma unroll
            for (int tm = 0; tm < 2; tm++) {
                uint32_t off = (uint32_t)((wm * 32 + tm * 16 + arow) * 80 + (kb + akof) * 2);
                ldsm_x4(ah[tm][0], ah[tm][1], ah[tm][2], ah[tm][3], uAh + off);
                ldsm_x4(al[tm][0], al[tm][1], al[tm][2], al[tm][3], uAl + off);
            }
            uint32_t bh[4][2], bl[4][2];
            #pragma unroll
            for (int p = 0; p < 2; p++) {
                uint32_t off = (uint32_t)((wn * 32 + p * 16 + brow) * 80 + (kb + bkof) * 2);
                ldsm_x4(bh[2 * p][0], bh[2 * p][1], bh[2 * p + 1][0], bh[2 * p + 1][1], uBh + off);
                ldsm_x4(bl[2 * p][0], bl[2 * p][1], bl[2 * p + 1][0], bl[2 * p + 1][1], uBl + off);
            }
            #pragma unroll
            for (int tm = 0; tm < 2; tm++)
                #pragma unroll
                for (int tn = 0; tn < 4; tn++) {
                    mma_bf16(d[tm][tn][0], d[tm][tn][1], d[tm][tn][2], d[tm][tn][3],
                             ah[tm][0], ah[tm][1], ah[tm][2], ah[tm][3],
                             bh[tn][0], bh[tn][1]);
                    mma_bf16(d[tm][tn][0], d[tm][tn][1], d[tm][tn][2], d[tm][tn][3],
                             ah[tm][0], ah[tm][1], ah[tm][2], ah[tm][3],
                             bl[tn][0], bl[tn][1]);
                    mma_bf16(d[tm][tn][0], d[tm][tn][1], d[tm][tn][2], d[tm][tn][3],
                             al[tm][0], al[tm][1], al[tm][2], al[tm][3],
                             bh[tn][0], bh[tn][1]);
                }
        }
        __syncthreads();
    }
    /* epilogue: thread t of warp holds (tq, 2*tr) pairs */
    int tq = lid >> 2, tr = lid & 3;
    #pragma unroll
    for (int tm = 0; tm < 2; tm++) {
        int r0 = m0 + wm * 32 + tm * 16 + tq;
        #pragma unroll
        for (int half = 0; half < 2; half++) {
            int r = r0 + half * 8;
            float rx = (EPI == 1) ? rnx[(b << 10) + r] : 0.f;
            float* orow = out + ((size_t)b * Mtot + r) * 1024;
            #pragma unroll
            for (int tn = 0; tn < 4; tn++) {
                int col = n0 + wn * 32 + tn * 8 + 2 * tr;
                float v0 = d[tm][tn][2 * half], v1 = d[tm][tn][2 * half + 1];
                float2 o;
                if (EPI == 1) {
                    o.x = 1.f - rx * rny[(b << 10) + col] * v0;
                    o.y = 1.f - rx * rny[(b << 10) + col + 1] * v1;
                } else {
                    o.x = v0; o.y = v1;
                }
                *(float2*)(orow + col) = o;
            }
        }
    }
}

/* ---------------- split helpers ---------------- */
__device__ __forceinline__ void bsplit(float v, unsigned short& h, unsigned short& l) {
    __nv_bfloat16 hh = __float2bfloat16(v);
    float rem = v - __bfloat162float(hh);
    __nv_bfloat16 ll = __float2bfloat16(rem);
    h = __bfloat16_as_ushort(hh);
    l = __bfloat16_as_ushort(ll);
}

/* transpose-split: in [b][512][1024] fp32 -> out [b][1024][512] bf16 hi/lo */
__global__ __launch_bounds__(256) void transpose_split(
    const float* __restrict__ x, unsigned short* __restrict__ oh,
    unsigned short* __restrict__ ol) {
    __shared__ float tb[32][33];
    int b = blockIdx.z;
    int i0 = blockIdx.x * 32, d0 = blockIdx.y * 32;
    int tx = threadIdx.x & 31, ty = threadIdx.x >> 5;
    const float* xb = x + (size_t)b * 512 * 1024;
    #pragma unroll
    for (int k = 0; k < 4; k++)
        tb[ty + k * 8][tx] = xb[(size_t)(d0 + ty + k * 8) * 1024 + i0 + tx];
    __syncthreads();
    #pragma unroll
    for (int k = 0; k < 4; k++) {
        int il = ty + k * 8;
        float v = tb[tx][il];
        unsigned short h, l;
        bsplit(v, h, l);
        size_t o = (size_t)b * 1024 * 512 + (size_t)(i0 + il) * 512 + d0 + tx;
        oh[o] = h; ol[o] = l;
    }
}

/* elementwise split: fp32 -> bf16 hi/lo pairs */
__global__ __launch_bounds__(256) void convert_split(
    const float* __restrict__ x, unsigned short* __restrict__ oh,
    unsigned short* __restrict__ ol, int npair) {
    int i = blockIdx.x * 256 + threadIdx.x;
    if (i >= npair) return;
    float2 v = ((const float2*)x)[i];
    unsigned short h0, l0, h1, l1;
    bsplit(v.x, h0, l0);
    bsplit(v.y, h1, l1);
    ((uint32_t*)oh)[i] = ((uint32_t)h1 << 16) | h0;
    ((uint32_t*)ol)[i] = ((uint32_t)l1 << 16) | l0;
}

/* pi = exp((u_i + v_j - C_ij)/eps)*1024, split to bf16 hi/lo [b][i][j] */
__global__ __launch_bounds__(256) void pi_gen(
    const float* __restrict__ C, const float* __restrict__ u,
    const float* __restrict__ v, unsigned short* __restrict__ ph,
    unsigned short* __restrict__ pl) {
    int b = blockIdx.y, i = blockIdx.x, t = threadIdx.x;
    float ui = u[(b << 10) + i];
    const float2* Crow = (const float2*)(C + ((size_t)(b << 10) + i) * 1024);
    const float2* vrow = (const float2*)(v + (b << 10));
    uint32_t* phr = (uint32_t*)(ph + ((size_t)(b << 10) + i) * 1024);
    uint32_t* plr = (uint32_t*)(pl + ((size_t)(b << 10) + i) * 1024);
    #pragma unroll
    for (int l = 0; l < 2; l++) {
        int j2 = t + l * 256;
        float2 c2 = Crow[j2], v2 = vrow[j2];
        float p0 = __expf((ui + v2.x - c2.x) * INV_EPS) * 1024.f;
        float p1 = __expf((ui + v2.y - c2.y) * INV_EPS) * 1024.f;
        unsigned short h0, l0, h1, l1;
        bsplit(p0, h0, l0);
        bsplit(p1, h1, l1);
        phr[j2] = ((uint32_t)h1 << 16) | h0;
        plr[j2] = ((uint32_t)l1 << 16) | l0;
    }
}

/* ---------------- small helpers ---------------- */
__device__ __forceinline__ float warpMax(float v) {
    #pragma unroll
    for (int o = 16; o; o >>= 1) v = fmaxf(v, __shfl_xor_sync(0xffffffffu, v, o));
    return v;
}
__device__ __forceinline__ float warpSum(float v) {
    #pragma unroll
    for (int o = 16; o; o >>= 1) v += __shfl_xor_sync(0xffffffffu, v, o);
    return v;
}

/* ---------------- 1/||x|| per point ---------------- */
__global__ __launch_bounds__(256) void rownorm(const float* __restrict__ x,
                                               float* __restrict__ rn) {
    int b = blockIdx.y;
    int i = blockIdx.x * 256 + threadIdx.x;
    const float* p = x + ((size_t)b * 512 << 10) + i;
    float s = 0.f;
    #pragma unroll 8
    for (int d = 0; d < 512; d++) {
        float v = p[(size_t)d << 10];
        s = fmaf(v, v, s);
    }
    rn[(b << 10) + i] = rsqrtf(s);
}

/* ---------------- Sinkhorn (R3 verbatim) ---------------- */
__global__ void zero_uv(float* u, float* v) {
    int i = blockIdx.x * blockDim.x + threadIdx.x;
    if (i < 4096) { u[i] = 0.f; v[i] = 0.f; }
}

__global__ __launch_bounds__(256) void u_update(const float* __restrict__ C,
                                                const float* __restrict__ v,
                                                float* __restrict__ u) {
    int b = blockIdx.y, i = blockIdx.x, t = threadIdx.x;
    const float4* C4 = (const float4*)(C + ((size_t)(b << 10) + i) * 1024);
    const float4* V4 = (const float4*)(v + (b << 10));
    float4 c = C4[t], vv = V4[t];
    float x0 = (vv.x - c.x) * INV_EPS;
    float x1 = (vv.y - c.y) * INV_EPS;
    float x2 = (vv.z - c.z) * INV_EPS;
    float x3 = (vv.w - c.w) * INV_EPS;
    float mx = fmaxf(fmaxf(x0, x1), fmaxf(x2, x3));
    __shared__ float redm[8], redq[8];
    mx = warpMax(mx);
    if ((t & 31) == 0) redm[t >> 5] = mx;
    __syncthreads();
    if (t < 32) {
        float z = (t < 8) ? redm[t] : -FLT_MAX;
        #pragma unroll
        for (int o = 4; o; o >>= 1) z = fmaxf(z, __shfl_xor_sync(0xffffffffu, z, o));
        if (t == 0) redm[0] = z;
    }
    __syncthreads();
    float bm = redm[0];
    float s = __expf(x0 - bm) + __expf(x1 - bm) + __expf(x2 - bm) + __expf(x3 - bm);
    s = warpSum(s);
    if ((t & 31) == 0) redq[t >> 5] = s;
    __syncthreads();
    if (t == 0) {
        float z = 0.f;
        #pragma unroll
        for (int q = 0; q < 8; q++) z += redq[q];
        u[(b << 10) + i] = EPS_S * (LOG_MU - (bm + __logf(z)));
    }
}

__global__ __launch_bounds__(256) void v_update(const float* __restrict__ C,
                                                const float* __restrict__ u,
                                                float* __restrict__ v) {
    int b = blockIdx.y;
    int tx = threadIdx.x, ty = threadIdx.y;
    int j = blockIdx.x * 32 + tx;
    const float* p = C + (size_t)b * 1048576 + j;
    const float* ub = u + (b << 10);
    float m0 = -FLT_MAX, s0 = 0.f, m1 = -FLT_MAX, s1 = 0.f;
    for (int i = ty; i < 1024; i += 16) {
        float xa = (ub[i] - p[(size_t)i << 10]) * INV_EPS;
        float xb = (ub[i + 8] - p[(size_t)(i + 8) << 10]) * INV_EPS;
        float n0 = fmaxf(m0, xa);
        s0 = s0 * __expf(m0 - n0) + __expf(xa - n0); m0 = n0;
        float n1 = fmaxf(m1, xb);
        s1 = s1 * __expf(m1 - n1) + __expf(xb - n1); m1 = n1;
    }
    float mm = fmaxf(m0, m1);
    float ss = s0 * __expf(m0 - mm) + s1 * __expf(m1 - mm);
    __shared__ float sm[8][32], sq[8][32];
    sm[ty][tx] = mm; sq[ty][tx] = ss;
    __syncthreads();
    if (ty == 0) {
        float M = mm, S = ss;
        #pragma unroll
        for (int q = 1; q < 8; q++) {
            float m2 = sm[q][tx], s2 = sq[q][tx];
            float nm = fmaxf(M, m2);
            S = S * __expf(M - nm) + s2 * __expf(m2 - nm);
            M = nm;
        }
        v[(b << 10) + j] = EPS_S * (LOG_MU - (M + __logf(S)));
    }
}

/* ---------------- per-(b,c) mean / 1/std of content ---------------- */
__global__ __launch_bounds__(128) void cmstd(const float* __restrict__ x,
                                             float* __restrict__ cm,
                                             float* __restrict__ rs) {
    int bc = blockIdx.x, t = threadIdx.x;
    const float* p = x + ((size_t)bc << 10);
    float s = 0.f, q = 0.f;
    #pragma unroll
    for (int l = 0; l < 8; l++) {
        float v = p[t + l * 128];
        s += v; q = fmaf(v, v, q);
    }
    s = warpSum(s); q = warpSum(q);
    __shared__ float rsm[4], rqm[4];
    if ((t & 31) == 0) { rsm[t >> 5] = s; rqm[t >> 5] = q; }
    __syncthreads();
    if (t == 0) {
        float S = rsm[0] + rsm[1] + rsm[2] + rsm[3];
        float Q = rqm[0] + rqm[1] + rqm[2] + rqm[3];
        float mean = S * (1.f / 1024.f);
        float var = Q * (1.f / 1024.f) - mean * mean;
        cm[bc] = mean;
        rs[bc] = rsqrtf(fmaxf(var, 0.f) + 1e-5f);
    }
}

/* ---------------- BatchNorm stats ---------------- */
__global__ __launch_bounds__(256) void bnstats(const float* __restrict__ x,
                                               const float* __restrict__ g,
                                               const float* __restrict__ be,
                                               int CO, float* __restrict__ scale,
                                               float* __restrict__ shift) {
    int c = blockIdx.x, t = threadIdx.x;
    float s = 0.f, q = 0.f;
    #pragma unroll
    for (int l = 0; l < 16; l++) {
        int idx = t + (l << 8);
        int bb = idx >> 10, p = idx & 1023;
        float v = x[((size_t)(bb * CO + c) << 10) + p];
        s += v; q = fmaf(v, v, q);
    }
    s = warpSum(s); q = warpSum(q);
    __shared__ float rsm[8], rqm[8];
    if ((t & 31) == 0) { rsm[t >> 5] = s; rqm[t >> 5] = q; }
    __syncthreads();
    if (t == 0) {
        float S = 0.f, Q = 0.f;
        #pragma unroll
        for (int w = 0; w < 8; w++) { S += rsm[w]; Q += rqm[w]; }
        float mean = S * (1.f / 4096.f);
        float var = Q * (1.f / 4096.f) - mean * mean;
        float sc = g[c] * rsqrtf(fmaxf(var, 0.f) + BN_EPS);
        scale[c] = sc;
        shift[c] = be[c] - mean * sc;
    }
}

/* ---------------- t = alpha * (content - cm) * rs + t ---------------- */
__global__ __launch_bounds__(256) void blend(float* __restrict__ t,
                                             const float* __restrict__ alpha,
                                             const float* __restrict__ content,
                                             const float* __restrict__ cm,
                                             const float* __restrict__ rs, int n4) {
    int i = blockIdx.x * 256 + threadIdx.x;
    if (i >= n4) return;
    int ch = i >> 8;
    float m = cm[ch], r = rs[ch];
    float4 a = ((const float4*)alpha)[i];
    float4 x = ((const float4*)content)[i];
    float4 tv = ((float4*)t)[i];
    tv.x = fmaf(a.x, (x.x - m) * r, tv.x);
    tv.y = fmaf(a.y, (x.y - m) * r, tv.y);
    tv.z = fmaf(a.z, (x.z - m) * r, tv.z);
    tv.w = fmaf(a.w, (x.w - m) * r, tv.w);
    ((float4*)t)[i] = tv;
}

/* ---------------- direct 3x3 conv (R3 verbatim) ---------------- */
template <int OCT, int SROWS, int NT, int CIT>
__global__ __launch_bounds__(NT) void conv3x3(
    const float* __restrict__ src0, const float* __restrict__ src1, int csplit,
    const float* __restrict__ sc, const float* __restrict__ sh,
    int CI, int CO, const float* __restrict__ W, const float* __restrict__ bias,
    float* __restrict__ out, int relu) {
    constexpr int NPIX = SROWS * 32;
    constexpr int PXT = NPIX / NT;
    __shared__ float s_in[CIT][SROWS + 2][34];
    __shared__ float s_w[CIT][9][OCT];
    int b = blockIdx.x, oc0 = blockIdx.y * OCT, r0 = blockIdx.z * SROWS;
    int tid = threadIdx.x;
    int rr[PXT], cc[PXT];
    #pragma unroll
    for (int p = 0; p < PXT; p++) {
        int px = tid + p * NT;
        rr[p] = px >> 5; cc[p] = px & 31;
    }
    float acc[OCT][PXT];
    #pragma unroll
    for (int o = 0; o < OCT; o++)
        #pragma unroll
        for (int p = 0; p < PXT; p++) acc[o][p] = 0.f;

    const int TOTIN = CIT * (SROWS + 2) * 34;
    const int TW = CIT * 9 * OCT;
    int use_aff = (sc != nullptr);

    #pragma unroll 1
    for (int ci0 = 0; ci0 < CI; ci0 += CIT) {
        #pragma unroll 1
        for (int idx = tid; idx < TOTIN; idx += NT) {
            int ci = idx / ((SROWS + 2) * 34);
            int rem = idx - ci * ((SROWS + 2) * 34);
            int r = rem / 34, c = rem - r * 34;
            int gy = r0 + r - 1, gx = c - 1;
            float v = 0.f;
            if ((unsigned)gy < 32u && (unsigned)gx < 32u) {
                int cig = ci0 + ci;
                const float* s = (cig < csplit)
                    ? (src0 + ((size_t)(b * csplit + cig) << 10))
                    : (src1 + ((size_t)(b * (CI - csplit) + (cig - csplit)) << 10));
                v = s[(gy << 5) + gx];
                if (use_aff) v = fmaf(v, sc[cig], sh[cig]);
            }
            (&s_in[0][0][0])[idx] = v;
        }
        #pragma unroll 1
        for (int idx = tid; idx < TW; idx += NT) {
            int ci = idx / (9 * OCT);
            int rem = idx - ci * (9 * OCT);
            int k = rem / OCT, oc = rem - k * OCT;
            float wv = 0.f;
            if (oc0 + oc < CO)
                wv = W[((size_t)(oc0 + oc) * CI + ci0 + ci) * 9 + k];
            (&s_w[0][0][0])[idx] = wv;
        }
        __syncthreads();
        #pragma unroll 1
        for (int ci = 0; ci < CIT; ci++) {
            #pragma unroll
            for (int ky = 0; ky < 3; ky++)
                #pragma unroll
                for (int kx = 0; kx < 3; kx++) {
                    float w[OCT];
                    #pragma unroll
                    for (int o4 = 0; o4 < OCT / 4; o4++)
                        *(float4*)&w[o4 * 4] = *(const float4*)&s_w[ci][ky * 3 + kx][o4 * 4];
                    #pragma unroll
                    for (int p = 0; p < PXT; p++) {
                        float v = s_in[ci][rr[p] + ky][cc[p] + kx];
                        #pragma unroll
                        for (int o = 0; o < OCT; o++)
                            acc[o][p] = fmaf(v, w[o], acc[o][p]);
                    }
                }
        }
        __syncthreads();
    }
    #pragma unroll
    for (int o = 0; o < OCT; o++) {
        if (oc0 + o >= CO) break;
        float bi = bias[oc0 + o];
        #pragma unroll
        for (int p = 0; p < PXT; p++) {
            float v = acc[o][p] + bi;
            if (relu) v = fmaxf(v, 0.f);
            out[((size_t)(b * CO + oc0 + o) << 10) + r0 * 32 + tid + p * NT] = v;
        }
    }
}

/* ---------------- host orchestration ---------------- */
extern "C" void kernel_launch(void* const* d_in, const int* in_sizes, int n_in,
                              void* d_out, int out_size) {
    const float* content = (const float*)d_in[0];
    const float* style   = (const float*)d_in[1];
    const float* w1 = (const float*)d_in[2];  const float* b1 = (const float*)d_in[3];
    const float* g1 = (const float*)d_in[4];  const float* be1 = (const float*)d_in[5];
    const float* w2 = (const float*)d_in[6];  const float* b2 = (const float*)d_in[7];
    const float* g2 = (const float*)d_in[8];  const float* be2 = (const float*)d_in[9];
    const float* w3 = (const float*)d_in[10]; const float* b3 = (const float*)d_in[11];
    const float* dw = (const float*)d_in[12]; const float* db = (const float*)d_in[13];
    float* out = (float*)d_out;
    (void)in_sizes; (void)n_in; (void)out_size;

    float *pC, *pu, *pv, *prnx, *prny, *pt, *pa1, *pa2, *palpha, *pcm, *prs, *pscale, *pshift;
    unsigned short *pcTh, *pcTl, *psTh, *psTl, *psfh, *psfl, *ppih, *ppil;
    cudaGetSymbolAddress((void**)&pC, g_C);
    cudaGetSymbolAddress((void**)&pu, g_u);
    cudaGetSymbolAddress((void**)&pv, g_v);
    cudaGetSymbolAddress((void**)&prnx, g_rnx);
    cudaGetSymbolAddress((void**)&prny, g_rny);
    cudaGetSymbolAddress((void**)&pt, g_t);
    cudaGetSymbolAddress((void**)&pa1, g_a1);
    cudaGetSymbolAddress((void**)&pa2, g_a2);
    cudaGetSymbolAddress((void**)&palpha, g_alpha);
    cudaGetSymbolAddress((void**)&pcm, g_cm);
    cudaGetSymbolAddress((void**)&prs, g_rs);
    cudaGetSymbolAddress((void**)&pscale, g_scale);
    cudaGetSymbolAddress((void**)&pshift, g_shift);
    cudaGetSymbolAddress((void**)&pcTh, g_cTh);
    cudaGetSymbolAddress((void**)&pcTl, g_cTl);
    cudaGetSymbolAddress((void**)&psTh, g_sTh);
    cudaGetSymbolAddress((void**)&psTl, g_sTl);
    cudaGetSymbolAddress((void**)&psfh, g_sfh);
    cudaGetSymbolAddress((void**)&psfl, g_sfl);
    cudaGetSymbolAddress((void**)&ppih, g_pih);
    cudaGetSymbolAddress((void**)&ppil, g_pil);

    /* bf16 split operand prep */
    transpose_split<<<dim3(32, 16, 4), 256>>>(content, pcTh, pcTl);
    transpose_split<<<dim3(32, 16, 4), 256>>>(style, psTh, psTl);
    convert_split<<<4096, 256>>>(style, psfh, psfl, 4 * 512 * 512);
    rownorm<<<dim3(4, 4), 256>>>(content, prnx);
    rownorm<<<dim3(4, 4), 256>>>(style, prny);

    /* cosine-cost matrix via tensor-core bf16 split GEMM */
    hmma_gemm<1><<<dim3(8, 16, 4), 256>>>(pcTh, pcTl, psTh, psTl,
                                          1024, 512, prnx, prny, pC);

    /* Sinkhorn, 20 iterations */
    zero_uv<<<16, 256>>>(pu, pv);
    for (int it = 0; it < 20; it++) {
        u_update<<<dim3(1024, 4), 256>>>(pC, pv, pu);
        v_update<<<dim3(32, 4), dim3(32, 8)>>>(pC, pu, pv);
    }

    /* pi (exp, split), then t = sf @ pi^T via tensor cores */
    pi_gen<<<dim3(1024, 4), 256>>>(pC, pu, pv, ppih, ppil);
    hmma_gemm<0><<<dim3(4, 16, 4), 256>>>(psfh, psfl, ppih, ppil,
                                          512, 1024, nullptr, nullptr, pt);

    /* content per-channel mean/std */
    cmstd<<<2048, 128>>>(content, pcm, prs);

    /* alpha predictor (R3 verbatim) */
    conv3x3<8, 16, 256, 8><<<dim3(4, 32, 2), 256>>>(pt, content, 512,
        nullptr, nullptr, 1024, 256, w1, b1, pa1, 1);
    bnstats<<<256, 256>>>(pa1, g1, be1, 256, pscale, pshift);
    conv3x3<8, 16, 256, 8><<<dim3(4, 32, 2), 256>>>(pa1, pa1, 256,
        pscale, pshift, 256, 256, w2, b2, pa2, 1);
    bnstats<<<256, 256>>>(pa2, g2, be2, 256, pscale, pshift);
    conv3x3<8, 16, 256, 8><<<dim3(4, 64, 2), 256>>>(pa2, pa2, 256,
        pscale, pshift, 256, 512, w3, b3, palpha, 0);

    /* t = alpha * c_normed + t, then decoder conv -> out */
    blend<<<2048, 256>>>(pt, palpha, content, pcm, prs, 4 * 512 * 256);
    conv3x3<4, 4, 128, 8><<<dim3(4, 1, 8), 128>>>(pt, pt, 512,
        nullptr, nullptr, 512, 3, dw, db, out, 0);
}

// round 9
// speedup vs baseline: 2.5635x; 2.1724x over previous
#include <cuda_runtime.h>
#include <cuda_bf16.h>
#include <cfloat>
#include <cstdint>

#define EPS_S   0.01f
#define INV_EPS 100.0f
#define LOG_MU  -6.93146200f   /* log(1/1024 + 1e-8) */
#define BN_EPS  1e-5f

typedef unsigned short ushort_t;

/* ---------------- scratch (device globals: no allocs allowed) -------------- */
__device__ float g_C[4 * 1024 * 1024];          /* cost matrix; later tblend NCHW */
__device__ float g_u[4096], g_v[4096];
__device__ float g_rnx[4096], g_rny[4096];
__device__ float g_t[4 * 1024 * 512];           /* t NHWC fp32 [pix][512] */
__device__ float g_a1[4 * 1024 * 256];          /* conv1 out NHWC */
__device__ float g_a2[4 * 1024 * 256];          /* conv2 out NHWC */
__device__ float g_alpha[4 * 1024 * 512];       /* conv3 out NHWC */
__device__ float g_cm[2048], g_rs[2048];
__device__ float g_scale[512], g_shift[512];
__device__ float g_ps[256 * 256], g_pq[256 * 256];
/* bf16 split buffers */
__device__ ushort_t g_cTh[4 * 1024 * 512], g_cTl[4 * 1024 * 512]; /* content NHWC */
__device__ ushort_t g_sTh[4 * 1024 * 512], g_sTl[4 * 1024 * 512]; /* style^T (cost B) */
__device__ ushort_t g_sfh[4 * 512 * 1024], g_sfl[4 * 512 * 1024]; /* style NCHW (transport B) */
__device__ ushort_t g_pih[4 * 1024 * 1024], g_pil[4 * 1024 * 1024];
__device__ ushort_t g_tth[4 * 1024 * 512], g_ttl[4 * 1024 * 512]; /* t NHWC bf16 */
__device__ ushort_t g_b1h[4 * 1024 * 256], g_b1l[4 * 1024 * 256]; /* bn1 NHWC bf16 */
__device__ ushort_t g_b2h[4 * 1024 * 256], g_b2l[4 * 1024 * 256];
__device__ ushort_t g_w1h[9 * 256 * 1024], g_w1l[9 * 256 * 1024];
__device__ ushort_t g_w2h[9 * 256 * 256],  g_w2l[9 * 256 * 256];
__device__ ushort_t g_w3h[9 * 512 * 256],  g_w3l[9 * 512 * 256];

__device__ __forceinline__ uint32_t smem_u32(const void* p) {
    uint32_t a;
    asm("{ .reg .u64 t; cvta.to.shared.u64 t, %1; cvt.u32.u64 %0, t; }"
        : "=r"(a) : "l"(p));
    return a;
}
__device__ __forceinline__ void ldsm_x4(uint32_t& r0, uint32_t& r1,
                                        uint32_t& r2, uint32_t& r3, uint32_t a) {
    asm volatile("ldmatrix.sync.aligned.m8n8.x4.shared.b16 {%0,%1,%2,%3}, [%4];"
                 : "=r"(r0), "=r"(r1), "=r"(r2), "=r"(r3) : "r"(a));
}
__device__ __forceinline__ void mma_bf16(float& d0, float& d1, float& d2, float& d3,
                                         uint32_t a0, uint32_t a1, uint32_t a2, uint32_t a3,
                                         uint32_t b0, uint32_t b1) {
    asm volatile(
        "mma.sync.aligned.m16n8k16.row.col.f32.bf16.bf16.f32 "
        "{%0,%1,%2,%3}, {%4,%5,%6,%7}, {%8,%9}, {%0,%1,%2,%3};"
        : "+f"(d0), "+f"(d1), "+f"(d2), "+f"(d3)
        : "r"(a0), "r"(a1), "r"(a2), "r"(a3), "r"(b0), "r"(b1));
}
__device__ __forceinline__ void bsplit(float v, ushort_t& h, ushort_t& l) {
    __nv_bfloat16 hh = __float2bfloat16(v);
    float rem = v - __bfloat162float(hh);
    __nv_bfloat16 ll = __float2bfloat16(rem);
    h = __bfloat16_as_ushort(hh);
    l = __bfloat16_as_ushort(ll);
}
__device__ __forceinline__ float bf2f(ushort_t x) {
    return __bfloat162float(__ushort_as_bfloat16(x));
}
__device__ __forceinline__ float warpSum(float v) {
    #pragma unroll
    for (int o = 16; o; o >>= 1) v += __shfl_xor_sync(0xffffffffu, v, o);
    return v;
}
__device__ __forceinline__ float warpMax(float v) {
    #pragma unroll
    for (int o = 16; o; o >>= 1) v = fmaxf(v, __shfl_xor_sync(0xffffffffu, v, o));
    return v;
}

/* ============ HMMA bf16 split GEMM (R8-verified core) ======================
   D[m,n] = sum_k A[m,k]B[n,k]. Block 128x64, 8 warps (4m x 2n), K chunk 32.
   EPI=1: cost (out = 1 - rnx*rny*acc, stride 1024)
   EPI=2: transport (out fp32 stride OS + bf16 split o2h/o2l)               */
template <int EPI>
__global__ __launch_bounds__(256) void hmma_gemm(
    const ushort_t* __restrict__ Ahi, const ushort_t* __restrict__ Alo,
    const ushort_t* __restrict__ Bhi, const ushort_t* __restrict__ Blo,
    int Mtot, int Ktot, int Nrows, int OS,
    const float* __restrict__ rnx, const float* __restrict__ rny,
    float* __restrict__ out, ushort_t* __restrict__ o2h, ushort_t* __restrict__ o2l) {
    __shared__ ushort_t sAh[128 * 40], sAl[128 * 40];
    __shared__ ushort_t sBh[64 * 40], sBl[64 * 40];
    int tid = threadIdx.x, wid = tid >> 5, lid = tid & 31;
    int b = blockIdx.z, m0 = blockIdx.x * 128, n0 = blockIdx.y * 64;
    int wm = wid & 3, wn = wid >> 2;
    size_t abase = (size_t)b * Mtot * Ktot;
    size_t bbase = (size_t)b * Nrows * Ktot;
    uint32_t uAh = smem_u32(sAh), uAl = smem_u32(sAl);
    uint32_t uBh = smem_u32(sBh), uBl = smem_u32(sBl);
    int arow = ((lid >> 3) & 1) * 8 + (lid & 7);
    int akof = (lid >> 4) * 8;
    int brow = (lid & 7) + ((lid >> 4) & 1) * 8;
    int bkof = ((lid >> 3) & 1) * 8;

    float d[2][4][4];
    #pragma unroll
    for (int i = 0; i < 2; i++)
        #pragma unroll
        for (int j = 0; j < 4; j++)
            #pragma unroll
            for (int q = 0; q < 4; q++) d[i][j][q] = 0.f;

    for (int k0 = 0; k0 < Ktot; k0 += 32) {
        #pragma unroll
        for (int l = 0; l < 2; l++) {
            int idx = tid + l * 256;
            int r = idx >> 2, seg = idx & 3;
            *(uint4*)(sAh + r * 40 + seg * 8) =
                *(const uint4*)(Ahi + abase + (size_t)(m0 + r) * Ktot + k0 + seg * 8);
            *(uint4*)(sAl + r * 40 + seg * 8) =
                *(const uint4*)(Alo + abase + (size_t)(m0 + r) * Ktot + k0 + seg * 8);
        }
        {
            int r = tid >> 2, seg = tid & 3;
            *(uint4*)(sBh + r * 40 + seg * 8) =
                *(const uint4*)(Bhi + bbase + (size_t)(n0 + r) * Ktot + k0 + seg * 8);
            *(uint4*)(sBl + r * 40 + seg * 8) =
                *(const uint4*)(Blo + bbase + (size_t)(n0 + r) * Ktot + k0 + seg * 8);
        }
        __syncthreads();
        #pragma unroll
        for (int ks = 0; ks < 2; ks++) {
            int kb = ks * 16;
            uint32_t ah[2][4], al[2][4];
            #pragma unroll
            for (int tm = 0; tm < 2; tm++) {
                uint32_t off = (uint32_t)((wm * 32 + tm * 16 + arow) * 80 + (kb + akof) * 2);
                ldsm_x4(ah[tm][0], ah[tm][1], ah[tm][2], ah[tm][3], uAh + off);
                ldsm_x4(al[tm][0], al[tm][1], al[tm][2], al[tm][3], uAl + off);
            }
            uint32_t bh[4][2], bl[4][2];
            #pragma unroll
            for (int p = 0; p < 2; p++) {
                uint32_t off = (uint32_t)((wn * 32 + p * 16 + brow) * 80 + (kb + bkof) * 2);
                ldsm_x4(bh[2 * p][0], bh[2 * p][1], bh[2 * p + 1][0], bh[2 * p + 1][1], uBh + off);
                ldsm_x4(bl[2 * p][0], bl[2 * p][1], bl[2 * p + 1][0], bl[2 * p + 1][1], uBl + off);
            }
            #pragma unroll
            for (int tm = 0; tm < 2; tm++)
                #pragma unroll
                for (int tn = 0; tn < 4; tn++) {
                    mma_bf16(d[tm][tn][0], d[tm][tn][1], d[tm][tn][2], d[tm][tn][3],
                             ah[tm][0], ah[tm][1], ah[tm][2], ah[tm][3], bh[tn][0], bh[tn][1]);
                    mma_bf16(d[tm][tn][0], d[tm][tn][1], d[tm][tn][2], d[tm][tn][3],
                             ah[tm][0], ah[tm][1], ah[tm][2], ah[tm][3], bl[tn][0], bl[tn][1]);
                    mma_bf16(d[tm][tn][0], d[tm][tn][1], d[tm][tn][2], d[tm][tn][3],
                             al[tm][0], al[tm][1], al[tm][2], al[tm][3], bh[tn][0], bh[tn][1]);
                }
        }
        __syncthreads();
    }
    int tq = lid >> 2, tr = lid & 3;
    #pragma unroll
    for (int tm = 0; tm < 2; tm++) {
        #pragma unroll
        for (int half = 0; half < 2; half++) {
            int r = m0 + wm * 32 + tm * 16 + tq + half * 8;
            #pragma unroll
            for (int tn = 0; tn < 4; tn++) {
                int col = n0 + wn * 32 + tn * 8 + 2 * tr;
                float v0 = d[tm][tn][2 * half], v1 = d[tm][tn][2 * half + 1];
                size_t oidx = ((size_t)b * Mtot + r) * OS + col;
                if (EPI == 1) {
                    float rx = rnx[(b << 10) + r];
                    float2 o;
                    o.x = 1.f - rx * rny[(b << 10) + col] * v0;
                    o.y = 1.f - rx * rny[(b << 10) + col + 1] * v1;
                    *(float2*)(out + oidx) = o;
                } else {
                    float2 o; o.x = v0; o.y = v1;
                    *(float2*)(out + oidx) = o;
                    ushort_t h0, l0, h1, l1;
                    bsplit(v0, h0, l0);
                    bsplit(v1, h1, l1);
                    *(uint32_t*)(o2h + oidx) = ((uint32_t)h1 << 16) | h0;
                    *(uint32_t*)(o2l + oidx) = ((uint32_t)l1 << 16) | l0;
                }
            }
        }
    }
}

/* ============ shifted-GEMM tensor conv (NHWC, split bf16) ==================
   out[pix][oc] = bias + sum_{ky,kx,ci} in[pix_shift][ci] * w[k][oc][ci].
   Block: 128 pixels (4 image rows) x 64 oc, 8 warps. ci chunk 32.
   smem input tile: 6 rows x 34 cols halo, rows padded to 40 ushort (80 B). */
__global__ __launch_bounds__(256) void conv_hmma(
    const ushort_t* __restrict__ Ah0, const ushort_t* __restrict__ Al0,
    const ushort_t* __restrict__ Ah1, const ushort_t* __restrict__ Al1,
    int csplit, int CI,
    const ushort_t* __restrict__ Wh, const ushort_t* __restrict__ Wl,
    int CO, const float* __restrict__ bias, int relu,
    float* __restrict__ out) {
    extern __shared__ unsigned char cs[];
    ushort_t* sIh = (ushort_t*)(cs);
    ushort_t* sIl = (ushort_t*)(cs + 16320);
    ushort_t* sBh = (ushort_t*)(cs + 32640);
    ushort_t* sBl = (ushort_t*)(cs + 48000);
    int tid = threadIdx.x, wid = tid >> 5, lid = tid & 31;
    int mt = blockIdx.x;
    int b = mt >> 3, r0 = (mt & 7) * 4;
    int n0 = blockIdx.y * 64;
    int wm = wid & 3, wn = wid >> 2;
    int arow = ((lid >> 3) & 1) * 8 + (lid & 7);
    int akof = (lid >> 4) * 8;
    int brow = (lid & 7) + ((lid >> 4) & 1) * 8;
    int bkof = ((lid >> 3) & 1) * 8;
    uint32_t uIh = smem_u32(sIh), uIl = smem_u32(sIl);
    uint32_t uBh = smem_u32(sBh), uBl = smem_u32(sBl);
    /* per-lane A base (pixel within tile) for each m16 tile */
    uint32_t aoff[2];
    #pragma unroll
    for (int tm = 0; tm < 2; tm++) {
        int p = wm * 32 + tm * 16 + arow;
        aoff[tm] = (uint32_t)(((p >> 5) * 34 + (p & 31)) * 80 + akof * 2);
    }
    uint32_t boff = (uint32_t)((wn * 32 + brow) * 80 + bkof * 2);

    float d[2][4][4];
    #pragma unroll
    for (int i = 0; i < 2; i++)
        #pragma unroll
        for (int j = 0; j < 4; j++)
            #pragma unroll
            for (int q = 0; q < 4; q++) d[i][j][q] = 0.f;

    for (int ch = 0; ch < CI; ch += 32) {
        const ushort_t* srcH;
        const ushort_t* srcL;
        int cw, coff;
        if (ch < csplit) { srcH = Ah0; srcL = Al0; cw = csplit; coff = ch; }
        else             { srcH = Ah1; srcL = Al1; cw = CI - csplit; coff = ch - csplit; }
        /* fill input tile: 204 smem pixels x 32 ci (hi/lo) */
        for (int idx = tid; idx < 816; idx += 256) {
            int sp = idx >> 2, seg = idx & 3;
            int srow = sp / 34, scol = sp - srow * 34;
            int gy = r0 - 1 + srow, gx = scol - 1;
            uint4 vh = make_uint4(0, 0, 0, 0), vl = make_uint4(0, 0, 0, 0);
            if ((unsigned)gy < 32u && (unsigned)gx < 32u) {
                size_t off = (size_t)(b * 1024 + (gy << 5) + gx) * cw + coff + seg * 8;
                vh = *(const uint4*)(srcH + off);
                vl = *(const uint4*)(srcL + off);
            }
            *(uint4*)(sIh + sp * 40 + seg * 8) = vh;
            *(uint4*)(sIl + sp * 40 + seg * 8) = vl;
        }
        #pragma unroll 1
        for (int ky = 0; ky < 3; ky++) {
            /* fill B: 3 kx x 64 oc x 32 ci */
            for (int idx = tid; idx < 768; idx += 256) {
                int kx = idx >> 8, rem = idx & 255, oc = rem >> 2, seg = rem & 3;
                size_t woff = ((size_t)((ky * 3 + kx) * CO + n0 + oc)) * CI + ch + seg * 8;
                *(uint4*)(sBh + (kx * 64 + oc) * 40 + seg * 8) = *(const uint4*)(Wh + woff);
                *(uint4*)(sBl + (kx * 64 + oc) * 40 + seg * 8) = *(const uint4*)(Wl + woff);
            }
            __syncthreads();
            #pragma unroll
            for (int kx = 0; kx < 3; kx++) {
                uint32_t shoff = (uint32_t)((ky * 34 + kx) * 80);
                #pragma unroll
                for (int ks = 0; ks < 2; ks++) {
                    uint32_t kso = (uint32_t)(ks * 32);
                    uint32_t ah[2][4], al[2][4];
                    #pragma unroll
                    for (int tm = 0; tm < 2; tm++) {
                        ldsm_x4(ah[tm][0], ah[tm][1], ah[tm][2], ah[tm][3],
                                uIh + aoff[tm] + shoff + kso);
                        ldsm_x4(al[tm][0], al[tm][1], al[tm][2], al[tm][3],
                                uIl + aoff[tm] + shoff + kso);
                    }
                    uint32_t bh[4][2], bl[4][2];
                    #pragma unroll
                    for (int p = 0; p < 2; p++) {
                        uint32_t off = boff + (uint32_t)(kx * 64 * 80 + p * 16 * 80) + kso;
                        ldsm_x4(bh[2 * p][0], bh[2 * p][1], bh[2 * p + 1][0], bh[2 * p + 1][1],
                                uBh + off);
                        ldsm_x4(bl[2 * p][0], bl[2 * p][1], bl[2 * p + 1][0], bl[2 * p + 1][1],
                                uBl + off);
                    }
                    #pragma unroll
                    for (int tm = 0; tm < 2; tm++)
                        #pragma unroll
                        for (int tn = 0; tn < 4; tn++) {
                            mma_bf16(d[tm][tn][0], d[tm][tn][1], d[tm][tn][2], d[tm][tn][3],
                                     ah[tm][0], ah[tm][1], ah[tm][2], ah[tm][3],
                                     bh[tn][0], bh[tn][1]);
                            mma_bf16(d[tm][tn][0], d[tm][tn][1], d[tm][tn][2], d[tm][tn][3],
                                     ah[tm][0], ah[tm][1], ah[tm][2], ah[tm][3],
                                     bl[tn][0], bl[tn][1]);
                            mma_bf16(d[tm][tn][0], d[tm][tn][1], d[tm][tn][2], d[tm][tn][3],
                                     al[tm][0], al[tm][1], al[tm][2], al[tm][3],
                                     bh[tn][0], bh[tn][1]);
                        }
                }
            }
            __syncthreads();
        }
    }
    int tq = lid >> 2, tr = lid & 3;
    #pragma unroll
    for (int tm = 0; tm < 2; tm++) {
        #pragma unroll
        for (int half = 0; half < 2; half++) {
            int pt = wm * 32 + tm * 16 + tq + half * 8;
            size_t prow = (size_t)(b * 1024 + r0 * 32 + pt) * CO;
            #pragma unroll
            for (int tn = 0; tn < 4; tn++) {
                int col = n0 + wn * 32 + tn * 8 + 2 * tr;
                float bi0 = bias[col], bi1 = bias[col + 1];
                float v0 = d[tm][tn][2 * half] + bi0;
                float v1 = d[tm][tn][2 * half + 1] + bi1;
                if (relu) { v0 = fmaxf(v0, 0.f); v1 = fmaxf(v1, 0.f); }
                float2 o; o.x = v0; o.y = v1;
                *(float2*)(out + prow + col) = o;
            }
        }
    }
}
static const int CONV_SMEM = 63360;

/* ---------------- prep kernels ---------------- */
__global__ __launch_bounds__(256) void transpose_split(
    const float* __restrict__ x, ushort_t* __restrict__ oh, ushort_t* __restrict__ ol) {
    __shared__ float tb[32][33];
    int b = blockIdx.z;
    int i0 = blockIdx.x * 32, d0 = blockIdx.y * 32;
    int tx = threadIdx.x & 31, ty = threadIdx.x >> 5;
    const float* xb = x + (size_t)b * 512 * 1024;
    #pragma unroll
    for (int k = 0; k < 4; k++)
        tb[ty + k * 8][tx] = xb[(size_t)(d0 + ty + k * 8) * 1024 + i0 + tx];
    __syncthreads();
    #pragma unroll
    for (int k = 0; k < 4; k++) {
        int il = ty + k * 8;
        float v = tb[tx][il];
        ushort_t h, l;
        bsplit(v, h, l);
        size_t o = (size_t)b * 1024 * 512 + (size_t)(i0 + il) * 512 + d0 + tx;
        oh[o] = h; ol[o] = l;
    }
}

__global__ __launch_bounds__(256) void convert_split(
    const float* __restrict__ x, ushort_t* __restrict__ oh,
    ushort_t* __restrict__ ol, int npair) {
    int i = blockIdx.x * 256 + threadIdx.x;
    if (i >= npair) return;
    float2 v = ((const float2*)x)[i];
    ushort_t h0, l0, h1, l1;
    bsplit(v.x, h0, l0);
    bsplit(v.y, h1, l1);
    ((uint32_t*)oh)[i] = ((uint32_t)h1 << 16) | h0;
    ((uint32_t*)ol)[i] = ((uint32_t)l1 << 16) | l0;
}

/* warp-per-row 1/||x|| on split-bf16 rows [4096][512] */
__global__ __launch_bounds__(256) void rownorm_t(const ushort_t* __restrict__ xh,
                                                 const ushort_t* __restrict__ xl,
                                                 float* __restrict__ rn) {
    int row = blockIdx.x * 8 + (threadIdx.x >> 5);
    int lane = threadIdx.x & 31;
    const uint4* ph = (const uint4*)(xh + (size_t)row * 512);
    const uint4* pl = (const uint4*)(xl + (size_t)row * 512);
    float s = 0.f;
    #pragma unroll
    for (int k = 0; k < 2; k++) {
        uint4 h4 = ph[lane + k * 32], l4 = pl[lane + k * 32];
        const ushort_t* hh = (const ushort_t*)&h4;
        const ushort_t* ll = (const ushort_t*)&l4;
        #pragma unroll
        for (int j = 0; j < 8; j++) {
            float v = bf2f(hh[j]) + bf2f(ll[j]);
            s = fmaf(v, v, s);
        }
    }
    s = warpSum(s);
    if (lane == 0) rn[row] = rsqrtf(s);
}

__global__ __launch_bounds__(256) void wprep(const float* __restrict__ w,
                                             ushort_t* __restrict__ wh,
                                             ushort_t* __restrict__ wl,
                                             int CO, int CI) {
    int i = blockIdx.x * 256 + threadIdx.x;
    if (i >= CO * CI) return;
    int oc = i / CI, ci = i - oc * CI;
    #pragma unroll
    for (int k = 0; k < 9; k++) {
        float v = w[(size_t)i * 9 + k];
        ushort_t h, l;
        bsplit(v, h, l);
        size_t o = ((size_t)k * CO + oc) * CI + ci;
        wh[o] = h; wl[o] = l;
    }
}

/* ---------------- Sinkhorn (R3 verbatim) ---------------- */
__global__ void zero_uv(float* u, float* v) {
    int i = blockIdx.x * blockDim.x + threadIdx.x;
    if (i < 4096) { u[i] = 0.f; v[i] = 0.f; }
}

__global__ __launch_bounds__(256) void u_update(const float* __restrict__ C,
                                                const float* __restrict__ v,
                                                float* __restrict__ u) {
    int b = blockIdx.y, i = blockIdx.x, t = threadIdx.x;
    const float4* C4 = (const float4*)(C + ((size_t)(b << 10) + i) * 1024);
    const float4* V4 = (const float4*)(v + (b << 10));
    float4 c = C4[t], vv = V4[t];
    float x0 = (vv.x - c.x) * INV_EPS;
    float x1 = (vv.y - c.y) * INV_EPS;
    float x2 = (vv.z - c.z) * INV_EPS;
    float x3 = (vv.w - c.w) * INV_EPS;
    float mx = fmaxf(fmaxf(x0, x1), fmaxf(x2, x3));
    __shared__ float redm[8], redq[8];
    mx = warpMax(mx);
    if ((t & 31) == 0) redm[t >> 5] = mx;
    __syncthreads();
    if (t < 32) {
        float z = (t < 8) ? redm[t] : -FLT_MAX;
        #pragma unroll
        for (int o = 4; o; o >>= 1) z = fmaxf(z, __shfl_xor_sync(0xffffffffu, z, o));
        if (t == 0) redm[0] = z;
    }
    __syncthreads();
    float bm = redm[0];
    float s = __expf(x0 - bm) + __expf(x1 - bm) + __expf(x2 - bm) + __expf(x3 - bm);
    s = warpSum(s);
    if ((t & 31) == 0) redq[t >> 5] = s;
    __syncthreads();
    if (t == 0) {
        float z = 0.f;
        #pragma unroll
        for (int q = 0; q < 8; q++) z += redq[q];
        u[(b << 10) + i] = EPS_S * (LOG_MU - (bm + __logf(z)));
    }
}

__global__ __launch_bounds__(256) void v_update(const float* __restrict__ C,
                                                const float* __restrict__ u,
                                                float* __restrict__ v) {
    int b = blockIdx.y;
    int tx = threadIdx.x, ty = threadIdx.y;
    int j = blockIdx.x * 32 + tx;
    const float* p = C + (size_t)b * 1048576 + j;
    const float* ub = u + (b << 10);
    float m0 = -FLT_MAX, s0 = 0.f, m1 = -FLT_MAX, s1 = 0.f;
    for (int i = ty; i < 1024; i += 16) {
        float xa = (ub[i] - p[(size_t)i << 10]) * INV_EPS;
        float xb = (ub[i + 8] - p[(size_t)(i + 8) << 10]) * INV_EPS;
        float n0 = fmaxf(m0, xa);
        s0 = s0 * __expf(m0 - n0) + __expf(xa - n0); m0 = n0;
        float n1 = fmaxf(m1, xb);
        s1 = s1 * __expf(m1 - n1) + __expf(xb - n1); m1 = n1;
    }
    float mm = fmaxf(m0, m1);
    float ss = s0 * __expf(m0 - mm) + s1 * __expf(m1 - mm);
    __shared__ float sm[8][32], sq[8][32];
    sm[ty][tx] = mm; sq[ty][tx] = ss;
    __syncthreads();
    if (ty == 0) {
        float M = mm, S = ss;
        #pragma unroll
        for (int q = 1; q < 8; q++) {
            float m2 = sm[q][tx], s2 = sq[q][tx];
            float nm = fmaxf(M, m2);
            S = S * __expf(M - nm) + s2 * __expf(m2 - nm);
            M = nm;
        }
        v[(b << 10) + j] = EPS_S * (LOG_MU - (M + __logf(S)));
    }
}

__global__ __launch_bounds__(256) void pi_gen(
    const float* __restrict__ C, const float* __restrict__ u,
    const float* __restrict__ v, ushort_t* __restrict__ ph,
    ushort_t* __restrict__ pl) {
    int b = blockIdx.y, i = blockIdx.x, t = threadIdx.x;
    float ui = u[(b << 10) + i];
    const float2* Crow = (const float2*)(C + ((size_t)(b << 10) + i) * 1024);
    const float2* vrow = (const float2*)(v + (b << 10));
    uint32_t* phr = (uint32_t*)(ph + ((size_t)(b << 10) + i) * 1024);
    uint32_t* plr = (uint32_t*)(pl + ((size_t)(b << 10) + i) * 1024);
    #pragma unroll
    for (int l = 0; l < 2; l++) {
        int j2 = t + l * 256;
        float2 c2 = Crow[j2], v2 = vrow[j2];
        float p0 = __expf((ui + v2.x - c2.x) * INV_EPS) * 1024.f;
        float p1 = __expf((ui + v2.y - c2.y) * INV_EPS) * 1024.f;
        ushort_t h0, l0, h1, l1;
        bsplit(p0, h0, l0);
        bsplit(p1, h1, l1);
        phr[j2] = ((uint32_t)h1 << 16) | h0;
        plr[j2] = ((uint32_t)l1 << 16) | l0;
    }
}

/* ---------------- per-(b,c) mean / 1/std of content (NCHW) ---------------- */
__global__ __launch_bounds__(128) void cmstd(const float* __restrict__ x,
                                             float* __restrict__ cm,
                                             float* __restrict__ rs) {
    int bc = blockIdx.x, t = threadIdx.x;
    const float* p = x + ((size_t)bc << 10);
    float s = 0.f, q = 0.f;
    #pragma unroll
    for (int l = 0; l < 8; l++) {
        float v = p[t + l * 128];
        s += v; q = fmaf(v, v, q);
    }
    s = warpSum(s); q = warpSum(q);
    __shared__ float rsm[4], rqm[4];
    if ((t & 31) == 0) { rsm[t >> 5] = s; rqm[t >> 5] = q; }
    __syncthreads();
    if (t == 0) {
        float S = rsm[0] + rsm[1] + rsm[2] + rsm[3];
        float Q = rqm[0] + rqm[1] + rqm[2] + rqm[3];
        float mean = S * (1.f / 1024.f);
        float var = Q * (1.f / 1024.f) - mean * mean;
        cm[bc] = mean;
        rs[bc] = rsqrtf(fmaxf(var, 0.f) + 1e-5f);
    }
}

/* ---------------- BatchNorm (NHWC, two-phase, deterministic) ---------------- */
__global__ __launch_bounds__(256) void bnpart(const float* __restrict__ x,
                                              float* __restrict__ ps,
                                              float* __restrict__ pq) {
    int slab = blockIdx.x, t = threadIdx.x;
    float s = 0.f, q = 0.f;
    #pragma unroll
    for (int i = 0; i < 16; i++) {
        float v = x[(size_t)(slab * 16 + i) * 256 + t];
        s += v; q = fmaf(v, v, q);
    }
    ps[slab * 256 + t] = s;
    pq[slab * 256 + t] = q;
}
__global__ void bnfin(const float* __restrict__ ps, const float* __restrict__ pq,
                      const float* __restrict__ g, const float* __restrict__ be,
                      float* __restrict__ scale, float* __restrict__ shift) {
    int c = threadIdx.x;
    float s = 0.f, q = 0.f;
    for (int k = 0; k < 256; k++) { s += ps[k * 256 + c]; q += pq[k * 256 + c]; }
    float mean = s * (1.f / 4096.f);
    float var = q * (1.f / 4096.f) - mean * mean;
    float sc = g[c] * rsqrtf(fmaxf(var, 0.f) + BN_EPS);
    scale[c] = sc;
    shift[c] = be[c] - mean * sc;
}
__global__ __launch_bounds__(256) void bn_split(const float* __restrict__ x,
                                                const float* __restrict__ scale,
                                                const float* __restrict__ shift,
                                                ushort_t* __restrict__ oh,
                                                ushort_t* __restrict__ ol) {
    int i = blockIdx.x * 256 + threadIdx.x;          /* 4096*256 */
    int c = i & 255;
    float v = fmaf(x[i], scale[c], shift[c]);
    ushort_t h, l;
    bsplit(v, h, l);
    oh[i] = h; ol[i] = l;
}

/* -------- blend + transpose: tblend NCHW = t + alpha*(content-cm)*rs ------- */
__global__ __launch_bounds__(256) void blend_T(const float* __restrict__ tn,
                                               const float* __restrict__ an,
                                               const float* __restrict__ content,
                                               const float* __restrict__ cm,
                                               const float* __restrict__ rs,
                                               float* __restrict__ outc) {
    __shared__ float ts[32][33], as_[32][33];
    int pix0 = blockIdx.x * 32, ch0 = blockIdx.y * 32;
    int tx = threadIdx.x & 31, ty = threadIdx.x >> 5;
    #pragma unroll
    for (int k = 0; k < 4; k++) {
        int p = pix0 + ty + k * 8;
        ts[ty + k * 8][tx]  = tn[(size_t)p * 512 + ch0 + tx];
        as_[ty + k * 8][tx] = an[(size_t)p * 512 + ch0 + tx];
    }
    __syncthreads();
    int b = pix0 >> 10;
    int pl = pix0 & 1023;
    #pragma unroll
    for (int k = 0; k < 4; k++) {
        int cl = ty + k * 8;
        int gch = b * 512 + ch0 + cl;
        float m = cm[gch], r = rs[gch];
        float c = content[(size_t)gch * 1024 + pl + tx];
        float v = fmaf(as_[tx][cl], (c - m) * r, ts[tx][cl]);
        outc[(size_t)gch * 1024 + pl + tx] = v;
    }
}

/* ---------------- decoder: direct 3x3 conv NCHW (R3 verbatim) -------------- */
template <int OCT, int SROWS, int NT, int CIT>
__global__ __launch_bounds__(NT) void conv3x3(
    const float* __restrict__ src0, int CI, int CO,
    const float* __restrict__ W, const float* __restrict__ bias,
    float* __restrict__ out) {
    constexpr int NPIX = SROWS * 32;
    constexpr int PXT = NPIX / NT;
    __shared__ float s_in[CIT][SROWS + 2][34];
    __shared__ float s_w[CIT][9][OCT];
    int b = blockIdx.x, oc0 = blockIdx.y * OCT, r0 = blockIdx.z * SROWS;
    int tid = threadIdx.x;
    int rr[PXT], cc[PXT];
    #pragma unroll
    for (int p = 0; p < PXT; p++) {
        int px = tid + p * NT;
        rr[p] = px >> 5; cc[p] = px & 31;
    }
    float acc[OCT][PXT];
    #pragma unroll
    for (int o = 0; o < OCT; o++)
        #pragma unroll
        for (int p = 0; p < PXT; p++) acc[o][p] = 0.f;

    const int TOTIN = CIT * (SROWS + 2) * 34;
    const int TW = CIT * 9 * OCT;
    #pragma unroll 1
    for (int ci0 = 0; ci0 < CI; ci0 += CIT) {
        #pragma unroll 1
        for (int idx = tid; idx < TOTIN; idx += NT) {
            int ci = idx / ((SROWS + 2) * 34);
            int rem = idx - ci * ((SROWS + 2) * 34);
            int r = rem / 34, c = rem - r * 34;
            int gy = r0 + r - 1, gx = c - 1;
            float v = 0.f;
            if ((unsigned)gy < 32u && (unsigned)gx < 32u)
                v = src0[((size_t)(b * CI + ci0 + ci) << 10) + (gy << 5) + gx];
            (&s_in[0][0][0])[idx] = v;
        }
        #pragma unroll 1
        for (int idx = tid; idx < TW; idx += NT) {
            int ci = idx / (9 * OCT);
            int rem = idx - ci * (9 * OCT);
            int k = rem / OCT, oc = rem - k * OCT;
            float wv = 0.f;
            if (oc0 + oc < CO)
                wv = W[((size_t)(oc0 + oc) * CI + ci0 + ci) * 9 + k];
            (&s_w[0][0][0])[idx] = wv;
        }
        __syncthreads();
        #pragma unroll 1
        for (int ci = 0; ci < CIT; ci++) {
            #pragma unroll
            for (int ky = 0; ky < 3; ky++)
                #pragma unroll
                for (int kx = 0; kx < 3; kx++) {
                    float w[OCT];
                    #pragma unroll
                    for (int o4 = 0; o4 < OCT / 4; o4++)
                        *(float4*)&w[o4 * 4] = *(const float4*)&s_w[ci][ky * 3 + kx][o4 * 4];
                    #pragma unroll
                    for (int p = 0; p < PXT; p++) {
                        float v = s_in[ci][rr[p] + ky][cc[p] + kx];
                        #pragma unroll
                        for (int o = 0; o < OCT; o++)
                            acc[o][p] = fmaf(v, w[o], acc[o][p]);
                    }
                }
        }
        __syncthreads();
    }
    #pragma unroll
    for (int o = 0; o < OCT; o++) {
        if (oc0 + o >= CO) break;
        float bi = bias[oc0 + o];
        #pragma unroll
        for (int p = 0; p < PXT; p++)
            out[((size_t)(b * CO + oc0 + o) << 10) + r0 * 32 + tid + p * NT] = acc[o][p] + bi;
    }
}

/* ---------------- host orchestration ---------------- */
extern "C" void kernel_launch(void* const* d_in, const int* in_sizes, int n_in,
                              void* d_out, int out_size) {
    const float* content = (const float*)d_in[0];
    const float* style   = (const float*)d_in[1];
    const float* w1 = (const float*)d_in[2];  const float* b1 = (const float*)d_in[3];
    const float* g1 = (const float*)d_in[4];  const float* be1 = (const float*)d_in[5];
    const float* w2 = (const float*)d_in[6];  const float* b2 = (const float*)d_in[7];
    const float* g2 = (const float*)d_in[8];  const float* be2 = (const float*)d_in[9];
    const float* w3 = (const float*)d_in[10]; const float* b3 = (const float*)d_in[11];
    const float* dw = (const float*)d_in[12]; const float* db = (const float*)d_in[13];
    float* out = (float*)d_out;
    (void)in_sizes; (void)n_in; (void)out_size;

    float *pC, *pu, *pv, *prnx, *prny, *pt, *pa1, *pa2, *palpha, *pcm, *prs,
          *pscale, *pshift, *pps, *ppq;
    ushort_t *pcTh, *pcTl, *psTh, *psTl, *psfh, *psfl, *ppih, *ppil,
             *ptth, *pttl, *pb1h, *pb1l, *pb2h, *pb2l,
             *pw1h, *pw1l, *pw2h, *pw2l, *pw3h, *pw3l;
    cudaGetSymbolAddress((void**)&pC, g_C);
    cudaGetSymbolAddress((void**)&pu, g_u);
    cudaGetSymbolAddress((void**)&pv, g_v);
    cudaGetSymbolAddress((void**)&prnx, g_rnx);
    cudaGetSymbolAddress((void**)&prny, g_rny);
    cudaGetSymbolAddress((void**)&pt, g_t);
    cudaGetSymbolAddress((void**)&pa1, g_a1);
    cudaGetSymbolAddress((void**)&pa2, g_a2);
    cudaGetSymbolAddress((void**)&palpha, g_alpha);
    cudaGetSymbolAddress((void**)&pcm, g_cm);
    cudaGetSymbolAddress((void**)&prs, g_rs);
    cudaGetSymbolAddress((void**)&pscale, g_scale);
    cudaGetSymbolAddress((void**)&pshift, g_shift);
    cudaGetSymbolAddress((void**)&pps, g_ps);
    cudaGetSymbolAddress((void**)&ppq, g_pq);
    cudaGetSymbolAddress((void**)&pcTh, g_cTh);
    cudaGetSymbolAddress((void**)&pcTl, g_cTl);
    cudaGetSymbolAddress((void**)&psTh, g_sTh);
    cudaGetSymbolAddress((void**)&psTl, g_sTl);
    cudaGetSymbolAddress((void**)&psfh, g_sfh);
    cudaGetSymbolAddress((void**)&psfl, g_sfl);
    cudaGetSymbolAddress((void**)&ppih, g_pih);
    cudaGetSymbolAddress((void**)&ppil, g_pil);
    cudaGetSymbolAddress((void**)&ptth, g_tth);
    cudaGetSymbolAddress((void**)&pttl, g_ttl);
    cudaGetSymbolAddress((void**)&pb1h, g_b1h);
    cudaGetSymbolAddress((void**)&pb1l, g_b1l);
    cudaGetSymbolAddress((void**)&pb2h, g_b2h);
    cudaGetSymbolAddress((void**)&pb2l, g_b2l);
    cudaGetSymbolAddress((void**)&pw1h, g_w1h);
    cudaGetSymbolAddress((void**)&pw1l, g_w1l);
    cudaGetSymbolAddress((void**)&pw2h, g_w2h);
    cudaGetSymbolAddress((void**)&pw2l, g_w2l);
    cudaGetSymbolAddress((void**)&pw3h, g_w3h);
    cudaGetSymbolAddress((void**)&pw3l, g_w3l);

    cudaFuncSetAttribute(conv_hmma, cudaFuncAttributeMaxDynamicSharedMemorySize, CONV_SMEM);

    /* operand prep */
    transpose_split<<<dim3(32, 16, 4), 256>>>(content, pcTh, pcTl);
    transpose_split<<<dim3(32, 16, 4), 256>>>(style, psTh, psTl);
    convert_split<<<4096, 256>>>(style, psfh, psfl, 4 * 512 * 512);
    rownorm_t<<<512, 256>>>(pcTh, pcTl, prnx);
    rownorm_t<<<512, 256>>>(psTh, psTl, prny);
    wprep<<<1024, 256>>>(w1, pw1h, pw1l, 256, 1024);
    wprep<<<256, 256>>>(w2, pw2h, pw2l, 256, 256);
    wprep<<<512, 256>>>(w3, pw3h, pw3l, 512, 256);

    /* cosine-cost matrix */
    hmma_gemm<1><<<dim3(8, 16, 4), 256>>>(pcTh, pcTl, psTh, psTl,
        1024, 512, 1024, 1024, prnx, prny, pC, nullptr, nullptr);

    /* Sinkhorn, 20 iterations */
    zero_uv<<<16, 256>>>(pu, pv);
    for (int it = 0; it < 20; it++) {
        u_update<<<dim3(1024, 4), 256>>>(pC, pv, pu);
        v_update<<<dim3(32, 4), dim3(32, 8)>>>(pC, pu, pv);
    }

    /* pi, then t = pi @ style^T -> NHWC fp32 + bf16 split */
    pi_gen<<<dim3(1024, 4), 256>>>(pC, pu, pv, ppih, ppil);
    hmma_gemm<2><<<dim3(8, 8, 4), 256>>>(ppih, ppil, psfh, psfl,
        1024, 1024, 512, 512, nullptr, nullptr, pt, ptth, pttl);

    cmstd<<<2048, 128>>>(content, pcm, prs);

    /* alpha predictor via tensor convs (NHWC) */
    conv_hmma<<<dim3(32, 4), 256, CONV_SMEM>>>(ptth, pttl, pcTh, pcTl, 512, 1024,
        pw1h, pw1l, 256, b1, 1, pa1);
    bnpart<<<256, 256>>>(pa1, pps, ppq);
    bnfin<<<1, 256>>>(pps, ppq, g1, be1, pscale, pshift);
    bn_split<<<4096, 256>>>(pa1, pscale, pshift, pb1h, pb1l);
    conv_hmma<<<dim3(32, 4), 256, CONV_SMEM>>>(pb1h, pb1l, pb1h, pb1l, 256, 256,
        pw2h, pw2l, 256, b2, 1, pa2);
    bnpart<<<256, 256>>>(pa2, pps, ppq);
    bnfin<<<1, 256>>>(pps, ppq, g2, be2, pscale, pshift);
    bn_split<<<4096, 256>>>(pa2, pscale, pshift, pb2h, pb2l);
    conv_hmma<<<dim3(32, 8), 256, CONV_SMEM>>>(pb2h, pb2l, pb2h, pb2l, 256, 256,
        pw3h, pw3l, 512, b3, 0, palpha);

    /* blend (transposed to NCHW), decoder conv */
    blend_T<<<dim3(128, 16), 256>>>(pt, palpha, content, pcm, prs, pC);
    conv3x3<4, 4, 128, 8><<<dim3(4, 1, 8), 128>>>(pC, 512, 3, dw, db, out);
}